// round 1
// baseline (speedup 1.0000x reference)
#include <cuda_runtime.h>
#include <cuda_bf16.h>
#include <math.h>

// HumanPoseModule: fused 6D-rot -> FK -> axis-angle
// Inputs: d_in[0] = glb_reduced_6d (BT,10,6) f32, d_in[1] = orientation_6d (BT,6,6) f32
// Output: (BT,24,3) f32

#define BT_TOTAL (1024 * 256)

// rows layout: m[0..2]=row0, m[3..5]=row1, m[6..8]=row2
__device__ __forceinline__ void rot6d_to_mat(const float* d6, float* m) {
    float a1x = d6[0], a1y = d6[1], a1z = d6[2];
    float a2x = d6[3], a2y = d6[4], a2z = d6[5];
    float n1 = sqrtf(a1x * a1x + a1y * a1y + a1z * a1z);
    float b1x = a1x / n1, b1y = a1y / n1, b1z = a1z / n1;
    float d = b1x * a2x + b1y * a2y + b1z * a2z;
    float b2x = a2x - d * b1x, b2y = a2y - d * b1y, b2z = a2z - d * b1z;
    float n2 = sqrtf(b2x * b2x + b2y * b2y + b2z * b2z);
    b2x /= n2; b2y /= n2; b2z /= n2;
    float b3x = b1y * b2z - b1z * b2y;
    float b3y = b1z * b2x - b1x * b2z;
    float b3z = b1x * b2y - b1y * b2x;
    m[0] = b1x; m[1] = b1y; m[2] = b1z;
    m[3] = b2x; m[4] = b2y; m[5] = b2z;
    m[6] = b3x; m[7] = b3y; m[8] = b3z;
}

// C = A * B
__device__ __forceinline__ void matmul(const float* A, const float* B, float* C) {
#pragma unroll
    for (int i = 0; i < 3; i++) {
#pragma unroll
        for (int j = 0; j < 3; j++) {
            C[i * 3 + j] = A[i * 3 + 0] * B[0 * 3 + j]
                         + A[i * 3 + 1] * B[1 * 3 + j]
                         + A[i * 3 + 2] * B[2 * 3 + j];
        }
    }
}

// C = A^T * B
__device__ __forceinline__ void matmulT(const float* A, const float* B, float* C) {
#pragma unroll
    for (int i = 0; i < 3; i++) {
#pragma unroll
        for (int j = 0; j < 3; j++) {
            C[i * 3 + j] = A[0 * 3 + i] * B[0 * 3 + j]
                         + A[1 * 3 + i] * B[1 * 3 + j]
                         + A[2 * 3 + i] * B[2 * 3 + j];
        }
    }
}

// matrix -> quaternion -> axis-angle (faithful to reference semantics)
__device__ __forceinline__ void mat_to_aa(const float* m, float* aa) {
    float m00 = m[0], m01 = m[1], m02 = m[2];
    float m10 = m[3], m11 = m[4], m12 = m[5];
    float m20 = m[6], m21 = m[7], m22 = m[8];

    float t0 = 1.0f + m00 + m11 + m22;
    float t1 = 1.0f + m00 - m11 - m22;
    float t2 = 1.0f - m00 + m11 - m22;
    float t3 = 1.0f - m00 - m11 + m22;
    float q0 = sqrtf(fmaxf(t0, 0.0f));
    float q1 = sqrtf(fmaxf(t1, 0.0f));
    float q2 = sqrtf(fmaxf(t2, 0.0f));
    float q3 = sqrtf(fmaxf(t3, 0.0f));

    // argmax with first-max semantics (strict >)
    float best = q0; int idx = 0;
    if (q1 > best) { best = q1; idx = 1; }
    if (q2 > best) { best = q2; idx = 2; }
    if (q3 > best) { best = q3; idx = 3; }

    float w, x, y, z;
    if (idx == 0) {
        w = q0 * q0; x = m21 - m12; y = m02 - m20; z = m10 - m01;
    } else if (idx == 1) {
        w = m21 - m12; x = q1 * q1; y = m10 + m01; z = m02 + m20;
    } else if (idx == 2) {
        w = m02 - m20; x = m10 + m01; y = q2 * q2; z = m12 + m21;
    } else {
        w = m10 - m01; x = m20 + m02; y = m21 + m12; z = q3 * q3;
    }
    float scale = 1.0f / (2.0f * fmaxf(best, 0.1f));
    w *= scale; x *= scale; y *= scale; z *= scale;

    float n = sqrtf(x * x + y * y + z * z);
    float half = atan2f(n, w);
    float angle = 2.0f * half;
    float s;
    if (fabsf(angle) < 1e-6f) {
        s = 0.5f - angle * angle * (1.0f / 48.0f);
    } else {
        s = sinf(half) / angle;
    }
    aa[0] = x / s;
    aa[1] = y / s;
    aa[2] = z / s;
}

__global__ __launch_bounds__(256)
void pose_kernel(const float* __restrict__ glb, const float* __restrict__ ori,
                 float* __restrict__ outp, int n) {
    int t = blockIdx.x * blockDim.x + threadIdx.x;
    if (t >= n) return;

    // Preload inputs with vector loads (both per-sample strides are 16B-aligned)
    float g[60];
    float o[36];
    {
        const float4* g4 = reinterpret_cast<const float4*>(glb + (size_t)t * 60);
        const float4* o4 = reinterpret_cast<const float4*>(ori + (size_t)t * 36);
#pragma unroll
        for (int i = 0; i < 15; i++) reinterpret_cast<float4*>(g)[i] = g4[i];
#pragma unroll
        for (int i = 0; i < 9; i++) reinterpret_cast<float4*>(o)[i] = o4[i];
    }

    float out[72];
#pragma unroll
    for (int i = 0; i < 72; i++) out[i] = 0.0f;  // ignored joints stay zero

    float root[9];
    rot6d_to_mat(o + 0, root);
    // joint 0: local = full[0] = root
    mat_to_aa(root, out + 0);

    float X[9], F[9], Ftmp[9], L[9];
    float F1[9], F2[9], F3[9], F6[9], F9[9], F12[9], F13[9], F14[9], F16[9], F17[9];

    // Reduced order in glb rows: [1,2,3,6,9,12,13,14,16,17]
    // Sensor order in ori rows:  [0,4,5,15,18,19]

    // joint 1 (reduced row 0), parent 0
    rot6d_to_mat(g + 0, X);  matmul(root, X, F1);  matmulT(root, F1, L);  mat_to_aa(L, out + 3);
    // joint 2 (r1), parent 0
    rot6d_to_mat(g + 6, X);  matmul(root, X, F2);  matmulT(root, F2, L);  mat_to_aa(L, out + 6);
    // joint 3 (r2), parent 0
    rot6d_to_mat(g + 12, X); matmul(root, X, F3);  matmulT(root, F3, L);  mat_to_aa(L, out + 9);
    // joint 4 (sensor row 1), parent 1
    rot6d_to_mat(o + 6, X);  matmul(root, X, Ftmp); matmulT(F1, Ftmp, L); mat_to_aa(L, out + 12);
    // joint 5 (sensor row 2), parent 2
    rot6d_to_mat(o + 12, X); matmul(root, X, Ftmp); matmulT(F2, Ftmp, L); mat_to_aa(L, out + 15);
    // joint 6 (r3), parent 3
    rot6d_to_mat(g + 18, X); matmul(root, X, F6);  matmulT(F3, F6, L);   mat_to_aa(L, out + 18);
    // joint 9 (r4), parent 6
    rot6d_to_mat(g + 24, X); matmul(root, X, F9);  matmulT(F6, F9, L);   mat_to_aa(L, out + 27);
    // joint 12 (r5), parent 9
    rot6d_to_mat(g + 30, X); matmul(root, X, F12); matmulT(F9, F12, L);  mat_to_aa(L, out + 36);
    // joint 13 (r6), parent 9
    rot6d_to_mat(g + 36, X); matmul(root, X, F13); matmulT(F9, F13, L);  mat_to_aa(L, out + 39);
    // joint 14 (r7), parent 9
    rot6d_to_mat(g + 42, X); matmul(root, X, F14); matmulT(F9, F14, L);  mat_to_aa(L, out + 42);
    // joint 15 (sensor row 3), parent 12
    rot6d_to_mat(o + 18, X); matmul(root, X, Ftmp); matmulT(F12, Ftmp, L); mat_to_aa(L, out + 45);
    // joint 16 (r8), parent 13
    rot6d_to_mat(g + 48, X); matmul(root, X, F16); matmulT(F13, F16, L); mat_to_aa(L, out + 48);
    // joint 17 (r9), parent 14
    rot6d_to_mat(g + 54, X); matmul(root, X, F17); matmulT(F14, F17, L); mat_to_aa(L, out + 51);
    // joint 18 (sensor row 4), parent 16
    rot6d_to_mat(o + 24, X); matmul(root, X, Ftmp); matmulT(F16, Ftmp, L); mat_to_aa(L, out + 54);
    // joint 19 (sensor row 5), parent 17
    rot6d_to_mat(o + 30, X); matmul(root, X, Ftmp); matmulT(F17, Ftmp, L); mat_to_aa(L, out + 57);

    (void)F; // silence unused warning if any

    // Vector stores: 72 floats = 18 float4, per-sample stride 288B (16B aligned)
    float4* out4 = reinterpret_cast<float4*>(outp + (size_t)t * 72);
#pragma unroll
    for (int i = 0; i < 18; i++) out4[i] = reinterpret_cast<float4*>(out)[i];
}

extern "C" void kernel_launch(void* const* d_in, const int* in_sizes, int n_in,
                              void* d_out, int out_size) {
    const float* glb = (const float*)d_in[0];
    const float* ori = (const float*)d_in[1];
    float* outp = (float*)d_out;
    int n = in_sizes[0] / 60;  // BT samples
    int threads = 256;
    int blocks = (n + threads - 1) / threads;
    pose_kernel<<<blocks, threads>>>(glb, ori, outp, n);
}